// round 15
// baseline (speedup 1.0000x reference)
#include <cuda_runtime.h>
#include <cstdint>
#include <cfloat>

#define C_CL   8
#define E_EX   8
#define D_DIM  4096
#define NF4    1024            // float4 per row
#define ROW    1025            // padded f4 stride in smem (conflict-free)
#define NTOT   (C_CL * E_EX)
#define TPB    512
#define TOKB   8               // tokens per block
#define SMEM_X (TOKB * ROW * 16)

// Read expert_ids[i] robustly whether delivered as int32 or int64.
// Content is arange(64): int32-view element 1 is 1 for int32, 0 for int64.
__device__ __forceinline__ int read_eid(const void* p, int i) {
    const int* p32 = (const int*)p;
    if (__ldg(p32 + 1) == 0) return (int)__ldg(((const long long*)p) + i);
    return __ldg(p32 + i);
}

// ---- packed f32x2 helpers (Blackwell FFMA2 only reachable via PTX) ----
__device__ __forceinline__ unsigned long long fma2(unsigned long long a,
                                                   unsigned long long b,
                                                   unsigned long long c) {
    unsigned long long d;
    asm("fma.rn.f32x2 %0, %1, %2, %3;" : "=l"(d) : "l"(a), "l"(b), "l"(c));
    return d;
}
__device__ __forceinline__ unsigned long long add2(unsigned long long a,
                                                   unsigned long long b) {
    unsigned long long d;
    asm("add.rn.f32x2 %0, %1, %2;" : "=l"(d) : "l"(a), "l"(b));
    return d;
}
__device__ __forceinline__ float sum2(unsigned long long v) {
    return __uint_as_float((unsigned)(v & 0xffffffffull)) +
           __uint_as_float((unsigned)(v >> 32));
}

// ============================================================================
// Fused kernel: stage 8 tokens' x into smem once; phase A computes cluster
// logits + per-token argmax in-block; phase B computes the selected cluster's
// expert logits (per-lane cluster-row gather -- same L1 wavefront cost as a
// broadcast) and scatters the 64-wide output rows. x touches DRAM exactly
// once; both main loops read x via LDS.
// Block = 512 thr = 16 warps = 16 D-splits of 256 dims; warp covers 8 tokens
// as two quads (A = tok 0-3, B = tok 4-7) with weights reused across quads.
// ============================================================================
__global__ void __launch_bounds__(TPB) fused_kernel(
    const float* __restrict__ x,
    const float* __restrict__ Wc,
    const float* __restrict__ We,
    const void* __restrict__ eids,
    float* __restrict__ out)
{
    extern __shared__ ulonglong2 sx[];          // [TOKB][ROW] padded x tile
    __shared__ float s_part[16][TOKB][8];       // [split][tok][c or e]
    __shared__ float s_logit[TOKB][8];
    __shared__ int   s_eid[TOKB][8];
    __shared__ int   s_cl[TOKB];

    const int tid  = threadIdx.x;
    const int w    = tid >> 5;
    const int lane = tid & 31;
    const int sub  = lane & 7;                  // 16B slice within 128B line
    const int tq   = lane >> 3;                 // quad token index (0..3)
    const int s    = w;                         // D-split (0..15), 256 dims

    // ---- Stage x tile: 8 tokens x 1024 f4, coalesced, deep MLP ----
    {
        const ulonglong2* __restrict__ xg = reinterpret_cast<const ulonglong2*>(
            x + (size_t)blockIdx.x * TOKB * D_DIM);
#pragma unroll
        for (int j = 0; j < 16; ++j) {
            const int idx = tid + j * TPB;      // 0..8191
            sx[(idx >> 10) * ROW + (idx & 1023)] = xg[idx];
        }
    }
    __syncthreads();

    // ================= Phase A: cluster logits =================
    {
        unsigned long long accA[C_CL], accB[C_CL];
#pragma unroll
        for (int c = 0; c < C_CL; ++c) { accA[c] = 0ull; accB[c] = 0ull; }

#pragma unroll 2
        for (int k = 0; k < 8; ++k) {
            const int f4 = s * 64 + k * 8 + sub;
            ulonglong2 xa = sx[tq * ROW + f4];
            ulonglong2 xb = sx[(4 + tq) * ROW + f4];
#pragma unroll
            for (int c = 0; c < C_CL; ++c) {
                ulonglong2 wv = reinterpret_cast<const ulonglong2*>(Wc + c * D_DIM)[f4];
                accA[c] = fma2(xa.x, wv.x, accA[c]);
                accA[c] = fma2(xa.y, wv.y, accA[c]);
                accB[c] = fma2(xb.x, wv.x, accB[c]);
                accB[c] = fma2(xb.y, wv.y, accB[c]);
            }
        }

        // Reduce across the 8 lanes of each quad.
#pragma unroll
        for (int d = 1; d <= 4; d <<= 1)
#pragma unroll
            for (int c = 0; c < C_CL; ++c) {
                accA[c] = add2(accA[c], __shfl_xor_sync(0xffffffffu, accA[c], d));
                accB[c] = add2(accB[c], __shfl_xor_sync(0xffffffffu, accB[c], d));
            }
#pragma unroll
        for (int c = 0; c < C_CL; ++c)
            if (sub == c) {
                s_part[s][tq][c]     = sum2(accA[c]);
                s_part[s][4 + tq][c] = sum2(accB[c]);
            }
    }
    __syncthreads();

    // Combine 16 splits + argmax: 64 threads = 8 tok x 8 c.
    if (tid < 64) {
        const int tl = tid >> 3;
        const int c  = tid & 7;
        float v = 0.0f;
#pragma unroll
        for (int sp = 0; sp < 16; ++sp) v += s_part[sp][tl][c];
        int bi = c;
#pragma unroll
        for (int d = 1; d <= 4; d <<= 1) {
            float vo = __shfl_xor_sync(0xffffffffu, v, d);
            int   io = __shfl_xor_sync(0xffffffffu, bi, d);
            if (vo > v || (vo == v && io < bi)) { v = vo; bi = io; }  // first-max
        }
        if (c == 0) s_cl[tl] = bi;
    }
    __syncthreads();

    // ================= Phase B: expert logits =================
    {
        const int cA = s_cl[tq];
        const int cB = s_cl[4 + tq];
        const float* wbA = We + (size_t)cA * (E_EX * D_DIM);
        const float* wbB = We + (size_t)cB * (E_EX * D_DIM);

        unsigned long long accA[E_EX], accB[E_EX];
#pragma unroll
        for (int e = 0; e < E_EX; ++e) { accA[e] = 0ull; accB[e] = 0ull; }

#pragma unroll 2
        for (int k = 0; k < 8; ++k) {
            const int f4 = s * 64 + k * 8 + sub;
            ulonglong2 xa = sx[tq * ROW + f4];
            ulonglong2 xb = sx[(4 + tq) * ROW + f4];
#pragma unroll
            for (int e = 0; e < E_EX; ++e) {
                ulonglong2 wa = reinterpret_cast<const ulonglong2*>(wbA + e * D_DIM)[f4];
                ulonglong2 wb = reinterpret_cast<const ulonglong2*>(wbB + e * D_DIM)[f4];
                accA[e] = fma2(xa.x, wa.x, accA[e]);
                accA[e] = fma2(xa.y, wa.y, accA[e]);
                accB[e] = fma2(xb.x, wb.x, accB[e]);
                accB[e] = fma2(xb.y, wb.y, accB[e]);
            }
        }

#pragma unroll
        for (int d = 1; d <= 4; d <<= 1)
#pragma unroll
            for (int e = 0; e < E_EX; ++e) {
                accA[e] = add2(accA[e], __shfl_xor_sync(0xffffffffu, accA[e], d));
                accB[e] = add2(accB[e], __shfl_xor_sync(0xffffffffu, accB[e], d));
            }
        __syncthreads();   // s_part reuse: phase-A combine readers are done
#pragma unroll
        for (int e = 0; e < E_EX; ++e)
            if (sub == e) {
                s_part[s][tq][e]     = sum2(accA[e]);
                s_part[s][4 + tq][e] = sum2(accB[e]);
            }
    }
    __syncthreads();

    // Combine splits + fetch expert ids: 64 threads = 8 tok x 8 e.
    if (tid < 64) {
        const int tl = tid >> 3;
        const int e  = tid & 7;
        float v = 0.0f;
#pragma unroll
        for (int sp = 0; sp < 16; ++sp) v += s_part[sp][tl][e];
        s_logit[tl][e] = v;
        s_eid[tl][e]   = read_eid(eids, s_cl[tl] * E_EX + e);
    }
    __syncthreads();

    // Scatter: 128 threads = 8 tokens x 16 float4 (full 64-col rows).
    if (tid < 128) {
        const int tl = tid >> 4;
        const int q  = tid & 15;
        const size_t tok = (size_t)blockIdx.x * TOKB + tl;
        float v[4];
#pragma unroll
        for (int j = 0; j < 4; ++j) {
            const int col = q * 4 + j;
            float val = -FLT_MAX;              // == jnp.finfo(float32).min
#pragma unroll
            for (int e = 0; e < E_EX; ++e)
                val = (s_eid[tl][e] == col) ? s_logit[tl][e] : val;
            v[j] = val;
        }
        reinterpret_cast<float4*>(out + tok * NTOT)[q] =
            make_float4(v[0], v[1], v[2], v[3]);
    }
}

extern "C" void kernel_launch(void* const* d_in, const int* in_sizes, int n_in,
                              void* d_out, int out_size) {
    const float* x    = (const float*)d_in[0];
    const float* Wc   = (const float*)d_in[1];
    const float* We   = (const float*)d_in[2];
    const void*  eids = d_in[3];
    float*       out  = (float*)d_out;

    const int D = in_sizes[2] / in_sizes[3];     // 4096
    const int T = in_sizes[0] / D;               // 8192
    (void)n_in; (void)out_size;

    cudaFuncSetAttribute(fused_kernel,
                         cudaFuncAttributeMaxDynamicSharedMemorySize, SMEM_X);
    fused_kernel<<<T / TOKB, TPB, SMEM_X>>>(x, Wc, We, eids, out);
}

// round 16
// speedup vs baseline: 1.3413x; 1.3413x over previous
#include <cuda_runtime.h>
#include <cstdint>
#include <cfloat>

// Problem constants (dataset-fixed; T derived at launch from in_sizes)
#define C_CL   8
#define E_EX   8
#define D_DIM  4096
#define NTOT   (C_CL * E_EX)   // 64 output slots
#define MAX_T  8192
#define NSPLIT 4               // D-dim splits (1024 dims per warp)

// Scratch (no allocs allowed)
__device__ int g_cnt[C_CL];
__device__ int g_cluster[MAX_T];
__device__ int g_bucket[C_CL * MAX_T];
__device__ int g_order[MAX_T];

__global__ void zero_cnt_kernel() {
    if (threadIdx.x < C_CL) g_cnt[threadIdx.x] = 0;
}

// Read expert_ids[i] robustly whether delivered as int32 or int64.
// Content is arange(64): int32-view element 1 is 1 for int32, 0 for int64.
__device__ __forceinline__ int read_eid(const void* p, int i) {
    const int* p32 = (const int*)p;
    if (__ldg(p32 + 1) == 0) return (int)__ldg(((const long long*)p) + i);
    return __ldg(p32 + i);
}

// ---- packed f32x2 helpers (Blackwell FFMA2 only reachable via PTX) ----
__device__ __forceinline__ unsigned long long fma2(unsigned long long a,
                                                   unsigned long long b,
                                                   unsigned long long c) {
    unsigned long long d;
    asm("fma.rn.f32x2 %0, %1, %2, %3;" : "=l"(d) : "l"(a), "l"(b), "l"(c));
    return d;
}
__device__ __forceinline__ unsigned long long add2(unsigned long long a,
                                                   unsigned long long b) {
    unsigned long long d;
    asm("add.rn.f32x2 %0, %1, %2;" : "=l"(d) : "l"(a), "l"(b));
    return d;
}
__device__ __forceinline__ float sum2(unsigned long long v) {
    return __uint_as_float((unsigned)(v & 0xffffffffull)) +
           __uint_as_float((unsigned)(v >> 32));
}

// ============================================================================
// Pass A: cluster logits + argmax + bucket scatter.
// Block = 8 warps = 2 token-groups(8 tokens) x 4 D-splits(1024 dims).
// Warp: 8 tokens as two quads (A,B). Main loop is a 2-deep software
// pipeline on the x stream (8 x-loads in flight) with each iteration's 8
// weight loads batched into registers before any FMA consumes them.
// ============================================================================
__global__ void __launch_bounds__(256, 2) cluster_kernel(
    const float* __restrict__ x,
    const float* __restrict__ Wc)
{
    __shared__ float s_part[2][NSPLIT][8][8];   // [tgl][split][tok_local][c]

    const int w    = threadIdx.x >> 5;
    const int lane = threadIdx.x & 31;
    const int tgl  = w >> 2;            // token-group within block (0..1)
    const int s    = w & 3;             // D-split (0..3)
    const int sub  = lane & 7;          // 16B slice within 128B line
    const int tq   = lane >> 3;         // quad index (0..3)
    const int tbase = blockIdx.x * 16 + tgl * 8;

    const ulonglong2* __restrict__ xrA =
        reinterpret_cast<const ulonglong2*>(x + (size_t)(tbase + tq) * D_DIM);
    const ulonglong2* __restrict__ xrB =
        reinterpret_cast<const ulonglong2*>(x + (size_t)(tbase + 4 + tq) * D_DIM);
    const int base = s * 256;           // ulonglong2 offset of this split

    unsigned long long accA[C_CL], accB[C_CL];
#pragma unroll
    for (int c = 0; c < C_CL; ++c) { accA[c] = 0ull; accB[c] = 0ull; }

    // 2-deep x pipeline.
    ulonglong2 xa0 = xrA[base + sub],      xb0 = xrB[base + sub];
    ulonglong2 xa1 = xrA[base + 8 + sub],  xb1 = xrB[base + 8 + sub];

#pragma unroll 2
    for (int k = 0; k < 32; ++k) {
        const int f4 = base + k * 8 + sub;
        const int fn = f4 + ((k < 30) ? 16 : 0);   // k+2 (clamped, always valid)
        ulonglong2 xa2 = xrA[fn];
        ulonglong2 xb2 = xrB[fn];

        ulonglong2 wv[C_CL];
#pragma unroll
        for (int c = 0; c < C_CL; ++c)
            wv[c] = reinterpret_cast<const ulonglong2*>(Wc + c * D_DIM)[f4];
#pragma unroll
        for (int c = 0; c < C_CL; ++c) {
            accA[c] = fma2(xa0.x, wv[c].x, accA[c]);
            accA[c] = fma2(xa0.y, wv[c].y, accA[c]);
            accB[c] = fma2(xb0.x, wv[c].x, accB[c]);
            accB[c] = fma2(xb0.y, wv[c].y, accB[c]);
        }
        xa0 = xa1; xb0 = xb1; xa1 = xa2; xb1 = xb2;
    }

    // Reduce across the 8 lanes of each quad.
#pragma unroll
    for (int d = 1; d <= 4; d <<= 1)
#pragma unroll
        for (int c = 0; c < C_CL; ++c) {
            accA[c] = add2(accA[c], __shfl_xor_sync(0xffffffffu, accA[c], d));
            accB[c] = add2(accB[c], __shfl_xor_sync(0xffffffffu, accB[c], d));
        }

#pragma unroll
    for (int c = 0; c < C_CL; ++c)
        if (sub == c) {
            s_part[tgl][s][tq][c]     = sum2(accA[c]);
            s_part[tgl][s][4 + tq][c] = sum2(accB[c]);
        }
    __syncthreads();

    // Combine splits + argmax: 128 threads = 2 tg x 8 tok x 8 c.
    if (threadIdx.x < 128) {
        const int tgl2 = threadIdx.x >> 6;
        const int tl   = (threadIdx.x >> 3) & 7;
        const int c    = threadIdx.x & 7;
        float v = s_part[tgl2][0][tl][c] + s_part[tgl2][1][tl][c]
                + s_part[tgl2][2][tl][c] + s_part[tgl2][3][tl][c];
        int bi = c;
#pragma unroll
        for (int d = 1; d <= 4; d <<= 1) {
            float vo = __shfl_xor_sync(0xffffffffu, v, d);
            int   io = __shfl_xor_sync(0xffffffffu, bi, d);
            if (vo > v || (vo == v && io < bi)) { v = vo; bi = io; }  // first-max
        }
        if (c == 0) {
            const int t = blockIdx.x * 16 + tgl2 * 8 + tl;
            g_cluster[t] = bi;
            int r = atomicAdd(&g_cnt[bi], 1);
            g_bucket[bi * MAX_T + r] = t;
        }
    }
}

// ============================================================================
// Middle: compact gapped buckets into cluster-major flat order (8 blocks),
// reversed within each bucket.
// ============================================================================
__global__ void __launch_bounds__(256) order_kernel() {
    const int c = blockIdx.x;
    int b = 0;
    for (int cc = 0; cc < c; ++cc) b += g_cnt[cc];
    const int n = g_cnt[c];
    for (int i = threadIdx.x; i < n; i += 256)
        g_order[b + i] = g_bucket[c * MAX_T + (n - 1 - i)];
}

// ============================================================================
// Pass B: expert logits + scatter. Same pipelined main loop; quads taken
// cluster-major from g_order (fast path shares weight registers).
// ============================================================================
__global__ void __launch_bounds__(256, 2) expert_kernel(
    const float* __restrict__ x,
    const float* __restrict__ We,
    const void* __restrict__ eids,
    float* __restrict__ out)
{
    __shared__ float s_part[2][NSPLIT][8][8];   // [tgl][split][tok_local][e]
    __shared__ float s_logit[16][8];
    __shared__ int   s_eid[16][8];
    __shared__ int   s_tok[16];
    __shared__ int   s_cl[16];

    const int w    = threadIdx.x >> 5;
    const int lane = threadIdx.x & 31;
    const int tgl  = w >> 2;
    const int s    = w & 3;
    const int sub  = lane & 7;
    const int tq   = lane >> 3;
    const int pbase = blockIdx.x * 16 + tgl * 8;

    const int tokA = g_order[pbase + tq];
    const int tokB = g_order[pbase + 4 + tq];
    const int cA   = g_cluster[tokA];
    const int cB   = g_cluster[tokB];
    if (s == 0 && sub == 0) {
        s_tok[tgl * 8 + tq]     = tokA;  s_cl[tgl * 8 + tq]     = cA;
        s_tok[tgl * 8 + 4 + tq] = tokB;  s_cl[tgl * 8 + 4 + tq] = cB;
    }

    const ulonglong2* __restrict__ xrA =
        reinterpret_cast<const ulonglong2*>(x + (size_t)tokA * D_DIM);
    const ulonglong2* __restrict__ xrB =
        reinterpret_cast<const ulonglong2*>(x + (size_t)tokB * D_DIM);
    const float* wbA = We + (size_t)cA * (E_EX * D_DIM);
    const float* wbB = We + (size_t)cB * (E_EX * D_DIM);
    const int base = s * 256;

    unsigned long long accA[E_EX], accB[E_EX];
#pragma unroll
    for (int e = 0; e < E_EX; ++e) { accA[e] = 0ull; accB[e] = 0ull; }

    if (__all_sync(0xffffffffu, cA == cB)) {
        // Fast path: shared weight registers for both quads; 2-deep x pipe.
        ulonglong2 xa0 = xrA[base + sub],      xb0 = xrB[base + sub];
        ulonglong2 xa1 = xrA[base + 8 + sub],  xb1 = xrB[base + 8 + sub];
#pragma unroll 2
        for (int k = 0; k < 32; ++k) {
            const int f4 = base + k * 8 + sub;
            const int fn = f4 + ((k < 30) ? 16 : 0);
            ulonglong2 xa2 = xrA[fn];
            ulonglong2 xb2 = xrB[fn];

            ulonglong2 wv[E_EX];
#pragma unroll
            for (int e = 0; e < E_EX; ++e)
                wv[e] = reinterpret_cast<const ulonglong2*>(wbA + e * D_DIM)[f4];
#pragma unroll
            for (int e = 0; e < E_EX; ++e) {
                accA[e] = fma2(xa0.x, wv[e].x, accA[e]);
                accA[e] = fma2(xa0.y, wv[e].y, accA[e]);
                accB[e] = fma2(xb0.x, wv[e].x, accB[e]);
                accB[e] = fma2(xb0.y, wv[e].y, accB[e]);
            }
            xa0 = xa1; xb0 = xb1; xa1 = xa2; xb1 = xb2;
        }
    } else {
        // Slow path (cluster-boundary warps): per-quad weight loads.
#pragma unroll 2
        for (int k = 0; k < 32; ++k) {
            const int f4 = base + k * 8 + sub;
            ulonglong2 xa = xrA[f4];
            ulonglong2 xb = xrB[f4];
#pragma unroll
            for (int e = 0; e < E_EX; ++e) {
                ulonglong2 wa = reinterpret_cast<const ulonglong2*>(wbA + e * D_DIM)[f4];
                ulonglong2 wb2 = reinterpret_cast<const ulonglong2*>(wbB + e * D_DIM)[f4];
                accA[e] = fma2(xa.x, wa.x, accA[e]);
                accA[e] = fma2(xa.y, wa.y, accA[e]);
                accB[e] = fma2(xb.x, wb2.x, accB[e]);
                accB[e] = fma2(xb.y, wb2.y, accB[e]);
            }
        }
    }

#pragma unroll
    for (int d = 1; d <= 4; d <<= 1)
#pragma unroll
        for (int e = 0; e < E_EX; ++e) {
            accA[e] = add2(accA[e], __shfl_xor_sync(0xffffffffu, accA[e], d));
            accB[e] = add2(accB[e], __shfl_xor_sync(0xffffffffu, accB[e], d));
        }

#pragma unroll
    for (int e = 0; e < E_EX; ++e)
        if (sub == e) {
            s_part[tgl][s][tq][e]     = sum2(accA[e]);
            s_part[tgl][s][4 + tq][e] = sum2(accB[e]);
        }
    __syncthreads();

    // Combine splits + fetch expert ids: 128 threads = 16 tok x 8 e.
    if (threadIdx.x < 128) {
        const int tl2 = threadIdx.x >> 3;
        const int e   = threadIdx.x & 7;
        const int tgl2 = tl2 >> 3, tli = tl2 & 7;
        s_logit[tl2][e] = s_part[tgl2][0][tli][e] + s_part[tgl2][1][tli][e]
                        + s_part[tgl2][2][tli][e] + s_part[tgl2][3][tli][e];
        s_eid[tl2][e] = read_eid(eids, s_cl[tl2] * E_EX + e);
    }
    __syncthreads();

    // Scatter: 256 threads = 16 tokens x 16 float4 (full 64-col rows).
    {
        const int tl3 = threadIdx.x >> 4;
        const int q   = threadIdx.x & 15;
        const int tok3 = s_tok[tl3];
        float v[4];
#pragma unroll
        for (int j = 0; j < 4; ++j) {
            const int col = q * 4 + j;
            float val = -FLT_MAX;              // == jnp.finfo(float32).min
#pragma unroll
            for (int e = 0; e < E_EX; ++e)
                val = (s_eid[tl3][e] == col) ? s_logit[tl3][e] : val;
            v[j] = val;
        }
        reinterpret_cast<float4*>(out + (size_t)tok3 * NTOT)[q] =
            make_float4(v[0], v[1], v[2], v[3]);
    }
}

extern "C" void kernel_launch(void* const* d_in, const int* in_sizes, int n_in,
                              void* d_out, int out_size) {
    const float* x    = (const float*)d_in[0];
    const float* Wc   = (const float*)d_in[1];
    const float* We   = (const float*)d_in[2];
    const void*  eids = d_in[3];
    float*       out  = (float*)d_out;

    const int D = in_sizes[2] / in_sizes[3];     // 4096
    const int T = in_sizes[0] / D;               // 8192
    (void)n_in; (void)out_size;

    zero_cnt_kernel<<<1, 32>>>();

    const int blocks = T / 16;           // 16 tokens per block
    cluster_kernel<<<blocks, 256>>>(x, Wc);
    order_kernel<<<C_CL, 256>>>();
    expert_kernel<<<blocks, 256>>>(x, We, eids, out);
}